// round 12
// baseline (speedup 1.0000x reference)
#include <cuda_runtime.h>
#include <cuda_fp16.h>
#include <cstdint>

// Problem constants.
#define NB 8192
#define NH 1024
#define NO 256
#define NE 16

// GEMM tiling: CTA = 64(M) x 128(N), K slabs of 64 halfs (128B rows), 4-stage pipeline.
#define BM 64
#define BN 128
#define BKS 64
#define NSLAB (NH / BKS)   // 16
#define THREADS 256
#define STAGES 4
#define A_STAGE_B 8192                  // 64 rows x 128 B
#define B_STAGE_B 16384                 // 128 rows x 128 B
#define A_OFF 0
#define B_OFF (STAGES * A_STAGE_B)      // 32768
#define BIAS_OFF (B_OFF + STAGES * B_STAGE_B)   // 98304
#define PRM_OFF (BIAS_OFF + BN * 4)             // 98816
#define MBAR_OFF (PRM_OFF + BM * 4)             // 99072
#define SMEM_TOTAL (MBAR_OFF + 64)              // 99136

// --- scratch (no allocs allowed) ---
__device__ int    g_perm[NB];
__device__ int    g_off[NE + 1];
__device__ int    g_counts[NE];
__device__ __half x16[NB * NH];                    // x fp16, original order
__device__ __half W16t[NE * 2 * NSLAB * 128 * 64]; // W fp16 tiled [e][nt][slab][row][64], chunk-swizzled

// swizzle: 16B-chunk c (0..7) in row r -> c ^ (r & 7)
#define SWZ(r, c) ((c) ^ ((r) & 7))

// ---------------- fused prep: bin (1 block) + x convert + W convert ----------------
// grid = 4097 x 256: [0,2048) x rows, [2048,4096) W rows, 4096 = bin.
__global__ __launch_bounds__(256)
void prep_kernel(const float* __restrict__ x, const float* __restrict__ W,
                 const int* __restrict__ num, const int* __restrict__ c, int cmap_n) {
    const int b = blockIdx.x;
    const int t = threadIdx.x;
    if (b < 2048) {
        const int row = b * 4 + (t >> 6);
        const int col = (t & 63) * 16;
        const float* src = x + (size_t)row * NH + col;
        float4 v0 = ((const float4*)src)[0];
        float4 v1 = ((const float4*)src)[1];
        float4 v2 = ((const float4*)src)[2];
        float4 v3 = ((const float4*)src)[3];
        __half2 h[8];
        h[0] = __floats2half2_rn(v0.x, v0.y);
        h[1] = __floats2half2_rn(v0.z, v0.w);
        h[2] = __floats2half2_rn(v1.x, v1.y);
        h[3] = __floats2half2_rn(v1.z, v1.w);
        h[4] = __floats2half2_rn(v2.x, v2.y);
        h[5] = __floats2half2_rn(v2.z, v2.w);
        h[6] = __floats2half2_rn(v3.x, v3.y);
        h[7] = __floats2half2_rn(v3.z, v3.w);
        __half* dst = x16 + (size_t)row * NH + col;
        ((uint4*)dst)[0] = *(uint4*)&h[0];
        ((uint4*)dst)[1] = *(uint4*)&h[4];
    } else if (b < 4096) {
        // W convert into tiled + swizzled layout: 2 global W rows per block
        const int og = (b - 2048) * 2 + (t >> 7);   // global W row 0..4095
        const int e  = og >> 8;
        const int o  = og & 255;
        const int nt = o >> 7;
        const int r  = o & 127;
        const int h0 = (t & 127) * 8;               // k offset (8 floats)
        const int slab = h0 >> 6;                   // 0..15
        const int cj   = (h0 & 63) >> 3;            // 16B chunk 0..7
        const float* src = W + (size_t)og * NH + h0;
        float4 v0 = ((const float4*)src)[0];
        float4 v1 = ((const float4*)src)[1];
        __half2 h[4];
        h[0] = __floats2half2_rn(v0.x, v0.y);
        h[1] = __floats2half2_rn(v0.z, v0.w);
        h[2] = __floats2half2_rn(v1.x, v1.y);
        h[3] = __floats2half2_rn(v1.z, v1.w);
        __half* dst = W16t + ((((size_t)(e * 2 + nt) * NSLAB + slab) * 128 + r) * 64
                              + SWZ(r, cj) * 8);
        *(uint4*)dst = *(uint4*)h;
    } else {
        // bin: single block
        __shared__ int cs[1024];
        __shared__ int scnt[NE];
        __shared__ int scur[NE];
        for (int i = t; i < cmap_n && i < 1024; i += 256) cs[i] = c[i] & (NE - 1);
        if (t < NE) scnt[t] = 0;
        __syncthreads();
        int le[NB / 256];
        #pragma unroll
        for (int j = 0; j < NB / 256; j++) {
            int i = t + j * 256;
            int idx = num[i];
            idx = min(max(idx, 0), cmap_n - 1);
            le[j] = cs[idx];
            atomicAdd(&scnt[le[j]], 1);
        }
        __syncthreads();
        if (t == 0) {
            int acc = 0;
            g_off[0] = 0;
            #pragma unroll
            for (int e = 0; e < NE; e++) {
                scur[e] = acc;
                acc += scnt[e];
                g_off[e + 1] = acc;
                g_counts[e] = scnt[e];
            }
        }
        __syncthreads();
        #pragma unroll
        for (int j = 0; j < NB / 256; j++) {
            int pos = atomicAdd(&scur[le[j]], 1);
            g_perm[pos] = t + j * 256;
        }
    }
}

// ---------------- helpers ----------------
__device__ __forceinline__ uint32_t smem_u32(const void* p) {
    uint32_t a;
    asm("{ .reg .u64 t; cvta.to.shared.u64 t, %1; cvt.u32.u64 %0, t; }" : "=r"(a) : "l"(p));
    return a;
}

__device__ __forceinline__ void cpasync16(uint32_t dst, const void* src) {
    asm volatile("cp.async.cg.shared.global [%0], [%1], 16;" :: "r"(dst), "l"(src));
}

__device__ __forceinline__ void ldsm_x4(uint32_t r[4], uint32_t addr) {
    asm volatile("ldmatrix.sync.aligned.m8n8.x4.shared.b16 {%0,%1,%2,%3}, [%4];"
                 : "=r"(r[0]), "=r"(r[1]), "=r"(r[2]), "=r"(r[3]) : "r"(addr));
}

__device__ __forceinline__ void mma_f16(float c[4], const uint32_t a[4],
                                        uint32_t b0, uint32_t b1) {
    asm volatile(
        "mma.sync.aligned.m16n8k16.row.col.f32.f16.f16.f32 "
        "{%0,%1,%2,%3}, {%4,%5,%6,%7}, {%8,%9}, {%0,%1,%2,%3};"
        : "+f"(c[0]), "+f"(c[1]), "+f"(c[2]), "+f"(c[3])
        : "r"(a[0]), "r"(a[1]), "r"(a[2]), "r"(a[3]), "r"(b0), "r"(b1));
}

__device__ __forceinline__ void mbar_wait(uint32_t mbar, uint32_t parity) {
    asm volatile(
        "{\n\t.reg .pred P;\n\t"
        "W%=:\n\t"
        "mbarrier.try_wait.parity.acquire.cta.shared::cta.b64 P, [%0], %1, 0x989680;\n\t"
        "@!P bra W%=;\n\t"
        "}" :: "r"(mbar), "r"(parity) : "memory");
}

__device__ __forceinline__ float sigf(float v) { return 1.f / (1.f + __expf(-v)); }

// ---------------- fp16 GEMM + bias + sigmoid; swizzled smem, bulk B ----------------
// grid = (2, 128, 16); dead tiles exit immediately.
__global__ __launch_bounds__(THREADS, 2)
void gemm_kernel(const float* __restrict__ bias, float* __restrict__ out) {
    const int e = blockIdx.z;
    const int rows = g_counts[e];
    const int m_start = blockIdx.y * BM;
    if (m_start >= rows) return;
    const int n_start = blockIdx.x * BN;
    const int base = g_off[e];

    extern __shared__ char smem[];
    const uint32_t sb = smem_u32(smem);
    float* bsm = (float*)(smem + BIAS_OFF);
    int*   prm = (int*)(smem + PRM_OFF);

    const int t    = threadIdx.x;
    const int lane = t & 31;
    const int wid  = t >> 5;
    const int g    = lane >> 2;
    const int tig  = lane & 3;
    const int g2   = lane >> 3;
    const int lr   = lane & 7;
    const int warp_m = (wid & 1) * 32;
    const int warp_n = (wid >> 1) * 32;

    if (t < BN) bsm[t] = bias[e * NO + n_start + t];
    if (t < BM) {
        int m = m_start + t;
        prm[t] = (m < rows) ? g_perm[base + m] : g_perm[base + m_start];
    }
    if (t == 0) {
        #pragma unroll
        for (int s = 0; s < STAGES; s++)
            asm volatile("mbarrier.init.shared.b64 [%0], 1;"
                         :: "r"(sb + MBAR_OFF + s * 8) : "memory");
    }
    __syncthreads();

    // A staging: thread t -> row t>>2, chunks c0=(t&3)*2, c0+1 (swizzled dst)
    const int arow = t >> 2;
    const int ac0  = (t & 3) * 2;
    const __half* agp = x16 + (size_t)prm[arow] * NH + ac0 * 8;
    const uint32_t adst0 = (uint32_t)(arow * 128 + SWZ(arow, ac0) * 16);
    const uint32_t adst1 = (uint32_t)(arow * 128 + SWZ(arow, ac0 + 1) * 16);
    // B bulk source: contiguous, pre-swizzled 16KB per slab
    const __half* bsrc = W16t + ((size_t)(e * 2 + blockIdx.x) * NSLAB) * (128 * 64);

    // ldmatrix row bases + swizzle keys
    uint32_t arb[2], asw[2], brb[2], bsw[2];
    const uint32_t cba = g2 >> 1;   // A logical chunk low bit
    const uint32_t cbb = g2 & 1;    // B logical chunk low bit
    #pragma unroll
    for (int mf = 0; mf < 2; mf++) {
        const int r = warp_m + mf * 16 + (g2 & 1) * 8 + lr;
        arb[mf] = (uint32_t)(r * 128);
        asw[mf] = (uint32_t)(r & 7);
    }
    #pragma unroll
    for (int p = 0; p < 2; p++) {
        const int r = warp_n + p * 16 + (g2 >> 1) * 8 + lr;
        brb[p] = (uint32_t)(r * 128);
        bsw[p] = (uint32_t)(r & 7);
    }

    float acc[2][4][4];
    #pragma unroll
    for (int i = 0; i < 2; i++)
        #pragma unroll
        for (int j = 0; j < 4; j++)
            #pragma unroll
            for (int q = 0; q < 4; q++) acc[i][j][q] = 0.f;

    auto issueA = [&](int ks, int s) {
        const uint32_t ab = sb + A_OFF + s * A_STAGE_B;
        cpasync16(ab + adst0, agp + ks * BKS);
        cpasync16(ab + adst1, agp + ks * BKS + 8);
    };
    auto issueB = [&](int ks, int s) {   // t==0 only
        const uint32_t mb = sb + MBAR_OFF + s * 8;
        asm volatile("mbarrier.arrive.expect_tx.shared.b64 _, [%0], %1;"
                     :: "r"(mb), "r"((uint32_t)B_STAGE_B) : "memory");
        asm volatile(
            "cp.async.bulk.shared::cluster.global.mbarrier::complete_tx::bytes "
            "[%0], [%1], %2, [%3];"
            :: "r"(sb + B_OFF + s * B_STAGE_B), "l"(bsrc + (size_t)ks * (128 * 64)),
               "r"((uint32_t)B_STAGE_B), "r"(mb) : "memory");
    };

    // prologue: stages 0..2
    #pragma unroll
    for (int s = 0; s < STAGES - 1; s++) {
        issueA(s, s);
        asm volatile("cp.async.commit_group;");
        if (t == 0) issueB(s, s);
    }

    for (int ks = 0; ks < NSLAB; ks++) {
        asm volatile("cp.async.wait_group %0;" :: "n"(STAGES - 2) : "memory");
        const int s = ks & (STAGES - 1);
        mbar_wait(sb + MBAR_OFF + s * 8, (ks >> 2) & 1);
        __syncthreads();   // orders data-ready AND stage-reuse

        const uint32_t ab = sb + A_OFF + s * A_STAGE_B;
        const uint32_t bb = sb + B_OFF + s * B_STAGE_B;
        #pragma unroll
        for (int kk = 0; kk < 4; kk++) {
            uint32_t a[2][4], b[2][4];
            #pragma unroll
            for (int mf = 0; mf < 2; mf++)
                ldsm_x4(a[mf], ab + arb[mf] + ((((kk << 1) | cba) ^ asw[mf]) << 4));
            #pragma unroll
            for (int p = 0; p < 2; p++)
                ldsm_x4(b[p], bb + brb[p] + ((((kk << 1) | cbb) ^ bsw[p]) << 4));
            #pragma unroll
            for (int mf = 0; mf < 2; mf++)
                #pragma unroll
                for (int nf = 0; nf < 4; nf++)
                    mma_f16(acc[mf][nf], a[mf], b[nf >> 1][(nf & 1) * 2],
                            b[nf >> 1][(nf & 1) * 2 + 1]);
        }

        const int ksn = ks + STAGES - 1;
        if (ksn < NSLAB) {
            issueA(ksn, ksn & (STAGES - 1));
            if (t == 0) issueB(ksn, ksn & (STAGES - 1));
        }
        asm volatile("cp.async.commit_group;");
    }

    // epilogue: bias + sigmoid, scatter rows through prm
    #pragma unroll
    for (int mf = 0; mf < 2; mf++) {
        #pragma unroll
        for (int h = 0; h < 2; h++) {
            const int rl = warp_m + mf * 16 + g + h * 8;
            if (m_start + rl < rows) {
                const int orow = prm[rl];
                #pragma unroll
                for (int nf = 0; nf < 4; nf++) {
                    const int col = warp_n + nf * 8 + 2 * tig;
                    float v0 = acc[mf][nf][h * 2 + 0] + bsm[col];
                    float v1 = acc[mf][nf][h * 2 + 1] + bsm[col + 1];
                    float2 o;
                    o.x = sigf(v0);
                    o.y = sigf(v1);
                    *(float2*)&out[(size_t)orow * NO + n_start + col] = o;
                }
            }
        }
    }
}

extern "C" void kernel_launch(void* const* d_in, const int* in_sizes, int n_in,
                              void* d_out, int out_size) {
    const float* x    = (const float*)d_in[0];   // [B, H]
    const float* W    = (const float*)d_in[1];   // [E, O, H]
    const float* bias = (const float*)d_in[2];   // [E, O]
    const int*   num  = (const int*)d_in[3];     // [B]    int32
    const int*   c    = (const int*)d_in[4];     // [CMAP] int32
    float* out = (float*)d_out;                  // [B, O]

    const int cmap_n = in_sizes[4];

    cudaFuncSetAttribute(gemm_kernel, cudaFuncAttributeMaxDynamicSharedMemorySize,
                         SMEM_TOTAL);

    prep_kernel<<<4097, 256>>>(x, W, num, c, cmap_n);

    dim3 grid(NO / BN, NB / BM, NE);   // (2, 128, 16)
    gemm_kernel<<<grid, THREADS, SMEM_TOTAL>>>(bias, out);
}

// round 13
// speedup vs baseline: 1.4714x; 1.4714x over previous
#include <cuda_runtime.h>
#include <cuda_fp16.h>
#include <cstdint>

// Problem constants.
#define NB 8192
#define NH 1024
#define NO 256
#define NE 16

// GEMM tiling: CTA = 64(M) x 128(N), K slabs of 32 halfs, 4-stage pipeline. (R11 config)
#define BM 64
#define BN 128
#define BKS 32
#define NSLAB (NH / BKS)   // 32
#define THREADS 256
#define STAGES 4
#define A_STAGE_B 4096                  // 64 rows x 64 B (swizzled chunks)
#define B_STAGE_B 8192                  // 128 rows x 64 B (swizzled chunks)
#define A_OFF 0
#define B_OFF (STAGES * A_STAGE_B)      // 16384
#define BIAS_OFF (B_OFF + STAGES * B_STAGE_B)   // 49152
#define PRM_OFF (BIAS_OFF + BN * 4)             // 49664
#define MBAR_OFF (PRM_OFF + BM * 4)             // 49920
#define SMEM_TOTAL (MBAR_OFF + 64)              // 49984

// --- scratch (no allocs allowed) ---
__device__ int    g_perm[NB];
__device__ int    g_off[NE + 1];
__device__ int    g_counts[NE];
__device__ __half W16t[NE * 2 * NSLAB * 128 * 32]; // W fp16 tiled [e][nt][slab][row][32], chunk-swizzled

// swizzle: 16B-chunk c (0..3) in row r -> c ^ ((r>>1)&3)
#define SWZ(r, c) ((c) ^ (((r) >> 1) & 3))

// ---------------- prep: W convert (2048 blocks) + bin (1 block) ----------------
__global__ __launch_bounds__(256)
void prep_kernel(const float* __restrict__ W,
                 const int* __restrict__ num, const int* __restrict__ c, int cmap_n) {
    const int b = blockIdx.x;
    const int t = threadIdx.x;
    if (b < 2048) {
        // W convert into tiled + swizzled layout: 2 global W rows per block
        const int og = b * 2 + (t >> 7);            // global W row 0..4095
        const int e  = og >> 8;
        const int o  = og & 255;
        const int nt = o >> 7;
        const int r  = o & 127;
        const int h0 = (t & 127) * 8;               // k offset (8 floats)
        const int slab = h0 >> 5;
        const int cj = (h0 & 31) >> 3;              // 16B chunk 0..3
        const float* src = W + (size_t)og * NH + h0;
        float4 v0 = ((const float4*)src)[0];
        float4 v1 = ((const float4*)src)[1];
        __half2 h[4];
        h[0] = __floats2half2_rn(v0.x, v0.y);
        h[1] = __floats2half2_rn(v0.z, v0.w);
        h[2] = __floats2half2_rn(v1.x, v1.y);
        h[3] = __floats2half2_rn(v1.z, v1.w);
        __half* dst = W16t + ((((size_t)(e * 2 + nt) * NSLAB + slab) * 128 + r) * 32
                              + SWZ(r, cj) * 8);
        *(uint4*)dst = *(uint4*)h;
    } else {
        // bin: single block
        __shared__ int cs[1024];
        __shared__ int scnt[NE];
        __shared__ int scur[NE];
        for (int i = t; i < cmap_n && i < 1024; i += 256) cs[i] = c[i] & (NE - 1);
        if (t < NE) scnt[t] = 0;
        __syncthreads();
        int le[NB / 256];
        #pragma unroll
        for (int j = 0; j < NB / 256; j++) {
            int i = t + j * 256;
            int idx = num[i];
            idx = min(max(idx, 0), cmap_n - 1);
            le[j] = cs[idx];
            atomicAdd(&scnt[le[j]], 1);
        }
        __syncthreads();
        if (t == 0) {
            int acc = 0;
            g_off[0] = 0;
            #pragma unroll
            for (int e = 0; e < NE; e++) {
                scur[e] = acc;
                acc += scnt[e];
                g_off[e + 1] = acc;
                g_counts[e] = scnt[e];
            }
        }
        __syncthreads();
        #pragma unroll
        for (int j = 0; j < NB / 256; j++) {
            int pos = atomicAdd(&scur[le[j]], 1);
            g_perm[pos] = t + j * 256;
        }
    }
}

// ---------------- helpers ----------------
__device__ __forceinline__ uint32_t smem_u32(const void* p) {
    uint32_t a;
    asm("{ .reg .u64 t; cvta.to.shared.u64 t, %1; cvt.u32.u64 %0, t; }" : "=r"(a) : "l"(p));
    return a;
}

__device__ __forceinline__ void ldsm_x4(uint32_t r[4], uint32_t addr) {
    asm volatile("ldmatrix.sync.aligned.m8n8.x4.shared.b16 {%0,%1,%2,%3}, [%4];"
                 : "=r"(r[0]), "=r"(r[1]), "=r"(r[2]), "=r"(r[3]) : "r"(addr));
}

__device__ __forceinline__ void mma_f16(float c[4], const uint32_t a[4],
                                        uint32_t b0, uint32_t b1) {
    asm volatile(
        "mma.sync.aligned.m16n8k16.row.col.f32.f16.f16.f32 "
        "{%0,%1,%2,%3}, {%4,%5,%6,%7}, {%8,%9}, {%0,%1,%2,%3};"
        : "+f"(c[0]), "+f"(c[1]), "+f"(c[2]), "+f"(c[3])
        : "r"(a[0]), "r"(a[1]), "r"(a[2]), "r"(a[3]), "r"(b0), "r"(b1));
}

__device__ __forceinline__ void mbar_wait(uint32_t mbar, uint32_t parity) {
    asm volatile(
        "{\n\t.reg .pred P;\n\t"
        "W%=:\n\t"
        "mbarrier.try_wait.parity.acquire.cta.shared::cta.b64 P, [%0], %1, 0x989680;\n\t"
        "@!P bra W%=;\n\t"
        "}" :: "r"(mbar), "r"(parity) : "memory");
}

__device__ __forceinline__ float sigf(float v) { return 1.f / (1.f + __expf(-v)); }

__device__ __forceinline__ void sts_cvt16(uint32_t dst, float4 v0, float4 v1) {
    __half2 h[4];
    h[0] = __floats2half2_rn(v0.x, v0.y);
    h[1] = __floats2half2_rn(v0.z, v0.w);
    h[2] = __floats2half2_rn(v1.x, v1.y);
    h[3] = __floats2half2_rn(v1.z, v1.w);
    uint4 u = *(uint4*)h;
    asm volatile("st.shared.v4.b32 [%0], {%1,%2,%3,%4};"
                 :: "r"(dst), "r"(u.x), "r"(u.y), "r"(u.z), "r"(u.w));
}

// ---------------- fp16 GEMM + bias + sigmoid; A = LDG fp32 + cvt, B = bulk ----------------
// grid = (2, 128, 16); dead tiles exit immediately.
__global__ __launch_bounds__(THREADS, 2)
void gemm_kernel(const float* __restrict__ x,
                 const float* __restrict__ bias, float* __restrict__ out) {
    const int e = blockIdx.z;
    const int rows = g_counts[e];
    const int m_start = blockIdx.y * BM;
    if (m_start >= rows) return;
    const int n_start = blockIdx.x * BN;
    const int base = g_off[e];

    extern __shared__ char smem[];
    const uint32_t sb = smem_u32(smem);
    float* bsm = (float*)(smem + BIAS_OFF);
    int*   prm = (int*)(smem + PRM_OFF);

    const int t    = threadIdx.x;
    const int lane = t & 31;
    const int wid  = t >> 5;
    const int g    = lane >> 2;
    const int tig  = lane & 3;
    const int g2   = lane >> 3;
    const int lr   = lane & 7;
    const int warp_m = (wid & 1) * 32;
    const int warp_n = (wid >> 1) * 32;

    if (t < BN) bsm[t] = bias[e * NO + n_start + t];
    if (t < BM) {
        int m = m_start + t;
        prm[t] = (m < rows) ? g_perm[base + m] : g_perm[base + m_start];
    }
    if (t == 0) {
        #pragma unroll
        for (int s = 0; s < STAGES; s++)
            asm volatile("mbarrier.init.shared.b64 [%0], 1;"
                         :: "r"(sb + MBAR_OFF + s * 8) : "memory");
    }
    __syncthreads();

    // A staging: thread t -> row t>>2, chunk t&3 (8 fp32 -> 8 fp16 = 16B), swizzled dst
    const int arow = t >> 2;
    const float* agp = x + (size_t)prm[arow] * NH + (t & 3) * 8;
    const uint32_t adst = (uint32_t)(arow * 64 + SWZ(arow, t & 3) * 16);
    // B bulk source: contiguous, pre-swizzled 8KB per slab
    const __half* bsrc = W16t + ((size_t)(e * 2 + blockIdx.x) * NSLAB) * (128 * 32);

    // ldmatrix row bases + swizzle keys
    uint32_t arb[2], asw[2], brb[2], bsw[2];
    const uint32_t cba = g2 >> 1;
    const uint32_t cbb = g2 & 1;
    #pragma unroll
    for (int mf = 0; mf < 2; mf++) {
        const int r = warp_m + mf * 16 + (g2 & 1) * 8 + lr;
        arb[mf] = (uint32_t)(r * 64);
        asw[mf] = (uint32_t)((r >> 1) & 3);
    }
    #pragma unroll
    for (int p = 0; p < 2; p++) {
        const int r = warp_n + p * 16 + (g2 >> 1) * 8 + lr;
        brb[p] = (uint32_t)(r * 64);
        bsw[p] = (uint32_t)((r >> 1) & 3);
    }

    float acc[2][4][4];
    #pragma unroll
    for (int i = 0; i < 2; i++)
        #pragma unroll
        for (int j = 0; j < 4; j++)
            #pragma unroll
            for (int q = 0; q < 4; q++) acc[i][j][q] = 0.f;

    auto issueB = [&](int ks, int s) {   // t==0 only
        const uint32_t mb = sb + MBAR_OFF + s * 8;
        asm volatile("mbarrier.arrive.expect_tx.shared.b64 _, [%0], %1;"
                     :: "r"(mb), "r"((uint32_t)B_STAGE_B) : "memory");
        asm volatile(
            "cp.async.bulk.shared::cluster.global.mbarrier::complete_tx::bytes "
            "[%0], [%1], %2, [%3];"
            :: "r"(sb + B_OFF + s * B_STAGE_B), "l"(bsrc + (size_t)ks * (128 * 32)),
               "r"((uint32_t)B_STAGE_B), "r"(mb) : "memory");
    };

    // prologue: stage A slabs 0..2 (LDG+cvt+STS), launch B bulks 0..2
    #pragma unroll
    for (int s = 0; s < STAGES - 1; s++) {
        float4 v0 = ((const float4*)(agp + s * BKS))[0];
        float4 v1 = ((const float4*)(agp + s * BKS))[1];
        sts_cvt16(sb + A_OFF + s * A_STAGE_B + adst, v0, v1);
        if (t == 0) issueB(s, s);
    }

    for (int ks = 0; ks < NSLAB; ks++) {
        const int s = ks & (STAGES - 1);
        mbar_wait(sb + MBAR_OFF + s * 8, (ks >> 2) & 1);
        __syncthreads();   // orders B-ready + A STS visibility + stage reuse

        // prefetch A for slab ks+3 (LDG latency covered by compute below)
        float4 v0, v1;
        const int ksn = ks + STAGES - 1;
        if (ksn < NSLAB) {
            v0 = ((const float4*)(agp + ksn * BKS))[0];
            v1 = ((const float4*)(agp + ksn * BKS))[1];
        }

        const uint32_t ab = sb + A_OFF + s * A_STAGE_B;
        const uint32_t bb = sb + B_OFF + s * B_STAGE_B;
        #pragma unroll
        for (int kk = 0; kk < 2; kk++) {
            uint32_t a[2][4], b[2][4];
            #pragma unroll
            for (int mf = 0; mf < 2; mf++)
                ldsm_x4(a[mf], ab + arb[mf] + (((cba | (kk << 1)) ^ asw[mf]) << 4));
            #pragma unroll
            for (int p = 0; p < 2; p++)
                ldsm_x4(b[p], bb + brb[p] + (((cbb | (kk << 1)) ^ bsw[p]) << 4));
            #pragma unroll
            for (int mf = 0; mf < 2; mf++)
                #pragma unroll
                for (int nf = 0; nf < 4; nf++)
                    mma_f16(acc[mf][nf], a[mf], b[nf >> 1][(nf & 1) * 2],
                            b[nf >> 1][(nf & 1) * 2 + 1]);
        }

        // stage A slab ks+3 into stage (ks-1)&3 (safe: all warps passed this iter's barrier)
        if (ksn < NSLAB) {
            sts_cvt16(sb + A_OFF + (ksn & (STAGES - 1)) * A_STAGE_B + adst, v0, v1);
            if (t == 0) issueB(ksn, ksn & (STAGES - 1));
        }
    }

    // epilogue: bias + sigmoid, scatter rows through prm
    #pragma unroll
    for (int mf = 0; mf < 2; mf++) {
        #pragma unroll
        for (int h = 0; h < 2; h++) {
            const int rl = warp_m + mf * 16 + g + h * 8;
            if (m_start + rl < rows) {
                const int orow = prm[rl];
                #pragma unroll
                for (int nf = 0; nf < 4; nf++) {
                    const int col = warp_n + nf * 8 + 2 * tig;
                    float v0 = acc[mf][nf][h * 2 + 0] + bsm[col];
                    float v1 = acc[mf][nf][h * 2 + 1] + bsm[col + 1];
                    float2 o;
                    o.x = sigf(v0);
                    o.y = sigf(v1);
                    *(float2*)&out[(size_t)orow * NO + n_start + col] = o;
                }
            }
        }
    }
}

extern "C" void kernel_launch(void* const* d_in, const int* in_sizes, int n_in,
                              void* d_out, int out_size) {
    const float* x    = (const float*)d_in[0];   // [B, H]
    const float* W    = (const float*)d_in[1];   // [E, O, H]
    const float* bias = (const float*)d_in[2];   // [E, O]
    const int*   num  = (const int*)d_in[3];     // [B]    int32
    const int*   c    = (const int*)d_in[4];     // [CMAP] int32
    float* out = (float*)d_out;                  // [B, O]

    const int cmap_n = in_sizes[4];

    cudaFuncSetAttribute(gemm_kernel, cudaFuncAttributeMaxDynamicSharedMemorySize,
                         SMEM_TOTAL);

    prep_kernel<<<2049, 256>>>(W, num, c, cmap_n);

    dim3 grid(NO / BN, NB / BM, NE);   // (2, 128, 16)
    gemm_kernel<<<grid, THREADS, SMEM_TOTAL>>>(x, bias, out);
}

// round 14
// speedup vs baseline: 1.5448x; 1.0499x over previous
#include <cuda_runtime.h>
#include <cuda_fp16.h>
#include <cstdint>

// Problem constants.
#define NB 8192
#define NH 1024
#define NO 256
#define NE 16

// GEMM tiling: CTA = 64(M) x 128(N), K slabs of 32 halfs, 4-stage pipeline.
#define BM 64
#define BN 128
#define BKS 32
#define NSLAB (NH / BKS)   // 32
#define THREADS 256
#define STAGES 4
#define A_STAGE_B 4096                  // 64 rows x 64 B (swizzled chunks)
#define B_STAGE_B 8192                  // 128 rows x 64 B (swizzled chunks)
#define A_OFF 0
#define B_OFF (STAGES * A_STAGE_B)      // 16384
#define BIAS_OFF (B_OFF + STAGES * B_STAGE_B)   // 49152
#define PRM_OFF (BIAS_OFF + BN * 4)             // 49664
#define MBAR_OFF (PRM_OFF + BM * 4)             // 49920
#define SMEM_TOTAL (MBAR_OFF + 64)              // 49984

// --- scratch (no allocs allowed) ---
__device__ int    g_perm[NB];
__device__ int    g_off[NE + 1];
__device__ int    g_counts[NE];
__device__ __half W16t[NE * 2 * NSLAB * 128 * 32]; // W fp16 tiled [e][nt][slab][row][32], chunk-swizzled

// swizzle: 16B-chunk c (0..3) in row r -> c ^ ((r>>1)&3)
#define SWZ(r, c) ((c) ^ (((r) >> 1) & 3))

// ---------------- prep: W convert (2048 blocks) + bin (1 block) ----------------
__global__ __launch_bounds__(256)
void prep_kernel(const float* __restrict__ W,
                 const int* __restrict__ num, const int* __restrict__ c, int cmap_n) {
    const int b = blockIdx.x;
    const int t = threadIdx.x;
    if (b < 2048) {
        const int og = b * 2 + (t >> 7);            // global W row 0..4095
        const int e  = og >> 8;
        const int o  = og & 255;
        const int nt = o >> 7;
        const int r  = o & 127;
        const int h0 = (t & 127) * 8;               // k offset (8 floats)
        const int slab = h0 >> 5;
        const int cj = (h0 & 31) >> 3;              // 16B chunk 0..3
        const float* src = W + (size_t)og * NH + h0;
        float4 v0 = ((const float4*)src)[0];
        float4 v1 = ((const float4*)src)[1];
        __half2 h[4];
        h[0] = __floats2half2_rn(v0.x, v0.y);
        h[1] = __floats2half2_rn(v0.z, v0.w);
        h[2] = __floats2half2_rn(v1.x, v1.y);
        h[3] = __floats2half2_rn(v1.z, v1.w);
        __half* dst = W16t + ((((size_t)(e * 2 + nt) * NSLAB + slab) * 128 + r) * 32
                              + SWZ(r, cj) * 8);
        *(uint4*)dst = *(uint4*)h;
    } else {
        // bin: single block
        __shared__ int cs[1024];
        __shared__ int scnt[NE];
        __shared__ int scur[NE];
        for (int i = t; i < cmap_n && i < 1024; i += 256) cs[i] = c[i] & (NE - 1);
        if (t < NE) scnt[t] = 0;
        __syncthreads();
        int le[NB / 256];
        #pragma unroll
        for (int j = 0; j < NB / 256; j++) {
            int i = t + j * 256;
            int idx = num[i];
            idx = min(max(idx, 0), cmap_n - 1);
            le[j] = cs[idx];
            atomicAdd(&scnt[le[j]], 1);
        }
        __syncthreads();
        if (t == 0) {
            int acc = 0;
            g_off[0] = 0;
            #pragma unroll
            for (int e = 0; e < NE; e++) {
                scur[e] = acc;
                acc += scnt[e];
                g_off[e + 1] = acc;
                g_counts[e] = scnt[e];
            }
        }
        __syncthreads();
        #pragma unroll
        for (int j = 0; j < NB / 256; j++) {
            int pos = atomicAdd(&scur[le[j]], 1);
            g_perm[pos] = t + j * 256;
        }
    }
}

// ---------------- helpers ----------------
__device__ __forceinline__ uint32_t smem_u32(const void* p) {
    uint32_t a;
    asm("{ .reg .u64 t; cvta.to.shared.u64 t, %1; cvt.u32.u64 %0, t; }" : "=r"(a) : "l"(p));
    return a;
}

__device__ __forceinline__ void ldsm_x4(uint32_t r[4], uint32_t addr) {
    asm volatile("ldmatrix.sync.aligned.m8n8.x4.shared.b16 {%0,%1,%2,%3}, [%4];"
                 : "=r"(r[0]), "=r"(r[1]), "=r"(r[2]), "=r"(r[3]) : "r"(addr));
}

__device__ __forceinline__ void mma_f16(float c[4], const uint32_t a[4],
                                        uint32_t b0, uint32_t b1) {
    asm volatile(
        "mma.sync.aligned.m16n8k16.row.col.f32.f16.f16.f32 "
        "{%0,%1,%2,%3}, {%4,%5,%6,%7}, {%8,%9}, {%0,%1,%2,%3};"
        : "+f"(c[0]), "+f"(c[1]), "+f"(c[2]), "+f"(c[3])
        : "r"(a[0]), "r"(a[1]), "r"(a[2]), "r"(a[3]), "r"(b0), "r"(b1));
}

__device__ __forceinline__ void mbar_wait(uint32_t mbar, uint32_t parity) {
    asm volatile(
        "{\n\t.reg .pred P;\n\t"
        "W%=:\n\t"
        "mbarrier.try_wait.parity.acquire.cta.shared::cta.b64 P, [%0], %1, 0x989680;\n\t"
        "@!P bra W%=;\n\t"
        "}" :: "r"(mbar), "r"(parity) : "memory");
}

__device__ __forceinline__ float sigf(float v) { return 1.f / (1.f + __expf(-v)); }

__device__ __forceinline__ void sts_cvt16(uint32_t dst, float4 v0, float4 v1) {
    __half2 h[4];
    h[0] = __floats2half2_rn(v0.x, v0.y);
    h[1] = __floats2half2_rn(v0.z, v0.w);
    h[2] = __floats2half2_rn(v1.x, v1.y);
    h[3] = __floats2half2_rn(v1.z, v1.w);
    uint4 u = *(uint4*)h;
    asm volatile("st.shared.v4.b32 [%0], {%1,%2,%3,%4};"
                 :: "r"(dst), "r"(u.x), "r"(u.y), "r"(u.z), "r"(u.w));
}

// ---------------- fp16 GEMM + bias + sigmoid; A = LDG fp32 (reg double-buffered) ----------------
// grid = (2, 128, 16); dead tiles exit immediately.
__global__ __launch_bounds__(THREADS, 2)
void gemm_kernel(const float* __restrict__ x,
                 const float* __restrict__ bias, float* __restrict__ out) {
    const int e = blockIdx.z;
    const int rows = g_counts[e];
    const int m_start = blockIdx.y * BM;
    if (m_start >= rows) return;
    const int n_start = blockIdx.x * BN;
    const int base = g_off[e];

    extern __shared__ char smem[];
    const uint32_t sb = smem_u32(smem);
    float* bsm = (float*)(smem + BIAS_OFF);
    int*   prm = (int*)(smem + PRM_OFF);

    const int t    = threadIdx.x;
    const int lane = t & 31;
    const int wid  = t >> 5;
    const int g    = lane >> 2;
    const int tig  = lane & 3;
    const int g2   = lane >> 3;
    const int lr   = lane & 7;
    const int warp_m = (wid & 1) * 32;
    const int warp_n = (wid >> 1) * 32;

    if (t < BN) bsm[t] = bias[e * NO + n_start + t];
    if (t < BM) {
        int m = m_start + t;
        prm[t] = (m < rows) ? g_perm[base + m] : g_perm[base + m_start];
    }
    if (t == 0) {
        #pragma unroll
        for (int s = 0; s < STAGES; s++)
            asm volatile("mbarrier.init.shared.b64 [%0], 1;"
                         :: "r"(sb + MBAR_OFF + s * 8) : "memory");
    }
    __syncthreads();

    // A staging: thread t -> row t>>2, chunk t&3 (8 fp32 -> 8 fp16 = 16B), swizzled dst
    const int arow = t >> 2;
    const float* agp = x + (size_t)prm[arow] * NH + (t & 3) * 8;
    const uint32_t adst = (uint32_t)(arow * 64 + SWZ(arow, t & 3) * 16);
    // B bulk source: contiguous, pre-swizzled 8KB per slab
    const __half* bsrc = W16t + ((size_t)(e * 2 + blockIdx.x) * NSLAB) * (128 * 32);

    // ldmatrix row bases + swizzle keys
    uint32_t arb[2], asw[2], brb[2], bsw[2];
    const uint32_t cba = g2 >> 1;
    const uint32_t cbb = g2 & 1;
    #pragma unroll
    for (int mf = 0; mf < 2; mf++) {
        const int r = warp_m + mf * 16 + (g2 & 1) * 8 + lr;
        arb[mf] = (uint32_t)(r * 64);
        asw[mf] = (uint32_t)((r >> 1) & 3);
    }
    #pragma unroll
    for (int p = 0; p < 2; p++) {
        const int r = warp_n + p * 16 + (g2 >> 1) * 8 + lr;
        brb[p] = (uint32_t)(r * 64);
        bsw[p] = (uint32_t)((r >> 1) & 3);
    }

    float acc[2][4][4];
    #pragma unroll
    for (int i = 0; i < 2; i++)
        #pragma unroll
        for (int j = 0; j < 4; j++)
            #pragma unroll
            for (int q = 0; q < 4; q++) acc[i][j][q] = 0.f;

    auto issueB = [&](int ks, int s) {   // t==0 only
        const uint32_t mb = sb + MBAR_OFF + s * 8;
        asm volatile("mbarrier.arrive.expect_tx.shared.b64 _, [%0], %1;"
                     :: "r"(mb), "r"((uint32_t)B_STAGE_B) : "memory");
        asm volatile(
            "cp.async.bulk.shared::cluster.global.mbarrier::complete_tx::bytes "
            "[%0], [%1], %2, [%3];"
            :: "r"(sb + B_OFF + s * B_STAGE_B), "l"(bsrc + (size_t)ks * (128 * 32)),
               "r"((uint32_t)B_STAGE_B), "r"(mb) : "memory");
    };

    // prologue: stage A slabs 0..2 (LDG+cvt+STS), launch B bulks 0..2
    #pragma unroll
    for (int s = 0; s < STAGES - 1; s++) {
        float4 v0 = ((const float4*)(agp + s * BKS))[0];
        float4 v1 = ((const float4*)(agp + s * BKS))[1];
        sts_cvt16(sb + A_OFF + s * A_STAGE_B + adst, v0, v1);
        if (t == 0) issueB(s, s);
    }
    // preload regs for slab 3 (consumed at bottom of iteration 0)
    float4 p0, p1;
    if (STAGES - 1 < NSLAB) {
        p0 = ((const float4*)(agp + (STAGES - 1) * BKS))[0];
        p1 = ((const float4*)(agp + (STAGES - 1) * BKS))[1];
    }

    for (int ks = 0; ks < NSLAB; ks++) {
        const int s = ks & (STAGES - 1);
        mbar_wait(sb + MBAR_OFF + s * 8, (ks >> 2) & 1);
        __syncthreads();   // orders B-ready + A STS visibility + stage reuse

        // top: issue LDG for slab ks+4 (consumed at bottom of NEXT iteration)
        float4 n0, n1;
        if (ks + STAGES < NSLAB) {
            n0 = ((const float4*)(agp + (ks + STAGES) * BKS))[0];
            n1 = ((const float4*)(agp + (ks + STAGES) * BKS))[1];
        }

        const uint32_t ab = sb + A_OFF + s * A_STAGE_B;
        const uint32_t bb = sb + B_OFF + s * B_STAGE_B;
        #pragma unroll
        for (int kk = 0; kk < 2; kk++) {
            uint32_t a[2][4], b[2][4];
            #pragma unroll
            for (int mf = 0; mf < 2; mf++)
                ldsm_x4(a[mf], ab + arb[mf] + (((cba | (kk << 1)) ^ asw[mf]) << 4));
            #pragma unroll
            for (int p = 0; p < 2; p++)
                ldsm_x4(b[p], bb + brb[p] + (((cbb | (kk << 1)) ^ bsw[p]) << 4));
            #pragma unroll
            for (int mf = 0; mf < 2; mf++)
                #pragma unroll
                for (int nf = 0; nf < 4; nf++)
                    mma_f16(acc[mf][nf], a[mf], b[nf >> 1][(nf & 1) * 2],
                            b[nf >> 1][(nf & 1) * 2 + 1]);
        }

        // bottom: stage A slab ks+3 from regs loaded one full iteration ago
        const int ksn = ks + STAGES - 1;
        if (ksn < NSLAB) {
            sts_cvt16(sb + A_OFF + (ksn & (STAGES - 1)) * A_STAGE_B + adst, p0, p1);
            if (t == 0) issueB(ksn, ksn & (STAGES - 1));
        }
        p0 = n0;
        p1 = n1;
    }

    // epilogue: bias + sigmoid, scatter rows through prm
    #pragma unroll
    for (int mf = 0; mf < 2; mf++) {
        #pragma unroll
        for (int h = 0; h < 2; h++) {
            const int rl = warp_m + mf * 16 + g + h * 8;
            if (m_start + rl < rows) {
                const int orow = prm[rl];
                #pragma unroll
                for (int nf = 0; nf < 4; nf++) {
                    const int col = warp_n + nf * 8 + 2 * tig;
                    float v0 = acc[mf][nf][h * 2 + 0] + bsm[col];
                    float v1 = acc[mf][nf][h * 2 + 1] + bsm[col + 1];
                    float2 o;
                    o.x = sigf(v0);
                    o.y = sigf(v1);
                    *(float2*)&out[(size_t)orow * NO + n_start + col] = o;
                }
            }
        }
    }
}

extern "C" void kernel_launch(void* const* d_in, const int* in_sizes, int n_in,
                              void* d_out, int out_size) {
    const float* x    = (const float*)d_in[0];   // [B, H]
    const float* W    = (const float*)d_in[1];   // [E, O, H]
    const float* bias = (const float*)d_in[2];   // [E, O]
    const int*   num  = (const int*)d_in[3];     // [B]    int32
    const int*   c    = (const int*)d_in[4];     // [CMAP] int32
    float* out = (float*)d_out;                  // [B, O]

    const int cmap_n = in_sizes[4];

    cudaFuncSetAttribute(gemm_kernel, cudaFuncAttributeMaxDynamicSharedMemorySize,
                         SMEM_TOTAL);

    prep_kernel<<<2049, 256>>>(W, num, c, cmap_n);

    dim3 grid(NO / BN, NB / BM, NE);   // (2, 128, 16)
    gemm_kernel<<<grid, THREADS, SMEM_TOTAL>>>(x, bias, out);
}

// round 15
// speedup vs baseline: 1.6088x; 1.0414x over previous
#include <cuda_runtime.h>
#include <cuda_fp16.h>
#include <cstdint>

// Problem constants.
#define NB 8192
#define NH 1024
#define NO 256
#define NE 16

// GEMM tiling: CTA = 64(M) x 128(N), K slabs of 32 halfs, 4-stage pipeline.
#define BM 64
#define BN 128
#define BKS 32
#define NSLAB (NH / BKS)   // 32
#define THREADS 256
#define STAGES 4
#define A_STAGE_B 4096                  // 64 rows x 64 B (swizzled chunks)
#define B_STAGE_B 8192                  // 128 rows x 64 B (swizzled chunks)
#define A_OFF 0
#define B_OFF (STAGES * A_STAGE_B)      // 16384
#define BIAS_OFF (B_OFF + STAGES * B_STAGE_B)   // 49152
#define PRM_OFF (BIAS_OFF + BN * 4)             // 49664
#define MBAR_OFF (PRM_OFF + BM * 4)             // 49920  (4 full + 4 empty = 64 B)
#define SMEM_TOTAL (MBAR_OFF + 64)              // 49984

// --- scratch (no allocs allowed) ---
__device__ int    g_perm[NB];
__device__ int    g_off[NE + 1];
__device__ int    g_counts[NE];
__device__ __half W16t[NE * 2 * NSLAB * 128 * 32]; // W fp16 tiled [e][nt][slab][row][32], chunk-swizzled

// swizzle: 16B-chunk c (0..3) in row r -> c ^ ((r>>1)&3)
#define SWZ(r, c) ((c) ^ (((r) >> 1) & 3))

// ---------------- prep: W convert (2048 blocks) + bin (1 block) ----------------
__global__ __launch_bounds__(256)
void prep_kernel(const float* __restrict__ W,
                 const int* __restrict__ num, const int* __restrict__ c, int cmap_n) {
    const int b = blockIdx.x;
    const int t = threadIdx.x;
    if (b < 2048) {
        const int og = b * 2 + (t >> 7);            // global W row 0..4095
        const int e  = og >> 8;
        const int o  = og & 255;
        const int nt = o >> 7;
        const int r  = o & 127;
        const int h0 = (t & 127) * 8;               // k offset (8 floats)
        const int slab = h0 >> 5;
        const int cj = (h0 & 31) >> 3;              // 16B chunk 0..3
        const float* src = W + (size_t)og * NH + h0;
        float4 v0 = ((const float4*)src)[0];
        float4 v1 = ((const float4*)src)[1];
        __half2 h[4];
        h[0] = __floats2half2_rn(v0.x, v0.y);
        h[1] = __floats2half2_rn(v0.z, v0.w);
        h[2] = __floats2half2_rn(v1.x, v1.y);
        h[3] = __floats2half2_rn(v1.z, v1.w);
        __half* dst = W16t + ((((size_t)(e * 2 + nt) * NSLAB + slab) * 128 + r) * 32
                              + SWZ(r, cj) * 8);
        *(uint4*)dst = *(uint4*)h;
    } else {
        // bin: single block
        __shared__ int cs[1024];
        __shared__ int scnt[NE];
        __shared__ int scur[NE];
        for (int i = t; i < cmap_n && i < 1024; i += 256) cs[i] = c[i] & (NE - 1);
        if (t < NE) scnt[t] = 0;
        __syncthreads();
        int le[NB / 256];
        #pragma unroll
        for (int j = 0; j < NB / 256; j++) {
            int i = t + j * 256;
            int idx = num[i];
            idx = min(max(idx, 0), cmap_n - 1);
            le[j] = cs[idx];
            atomicAdd(&scnt[le[j]], 1);
        }
        __syncthreads();
        if (t == 0) {
            int acc = 0;
            g_off[0] = 0;
            #pragma unroll
            for (int e = 0; e < NE; e++) {
                scur[e] = acc;
                acc += scnt[e];
                g_off[e + 1] = acc;
                g_counts[e] = scnt[e];
            }
        }
        __syncthreads();
        #pragma unroll
        for (int j = 0; j < NB / 256; j++) {
            int pos = atomicAdd(&scur[le[j]], 1);
            g_perm[pos] = t + j * 256;
        }
    }
}

// ---------------- helpers ----------------
__device__ __forceinline__ uint32_t smem_u32(const void* p) {
    uint32_t a;
    asm("{ .reg .u64 t; cvta.to.shared.u64 t, %1; cvt.u32.u64 %0, t; }" : "=r"(a) : "l"(p));
    return a;
}

__device__ __forceinline__ void ldsm_x4(uint32_t r[4], uint32_t addr) {
    asm volatile("ldmatrix.sync.aligned.m8n8.x4.shared.b16 {%0,%1,%2,%3}, [%4];"
                 : "=r"(r[0]), "=r"(r[1]), "=r"(r[2]), "=r"(r[3]) : "r"(addr));
}

__device__ __forceinline__ void mma_f16(float c[4], const uint32_t a[4],
                                        uint32_t b0, uint32_t b1) {
    asm volatile(
        "mma.sync.aligned.m16n8k16.row.col.f32.f16.f16.f32 "
        "{%0,%1,%2,%3}, {%4,%5,%6,%7}, {%8,%9}, {%0,%1,%2,%3};"
        : "+f"(c[0]), "+f"(c[1]), "+f"(c[2]), "+f"(c[3])
        : "r"(a[0]), "r"(a[1]), "r"(a[2]), "r"(a[3]), "r"(b0), "r"(b1));
}

__device__ __forceinline__ void mbar_wait(uint32_t mbar, uint32_t parity) {
    asm volatile(
        "{\n\t.reg .pred P;\n\t"
        "W%=:\n\t"
        "mbarrier.try_wait.parity.acquire.cta.shared::cta.b64 P, [%0], %1, 0x989680;\n\t"
        "@!P bra W%=;\n\t"
        "}" :: "r"(mbar), "r"(parity) : "memory");
}

__device__ __forceinline__ void mbar_arrive(uint32_t mbar) {
    asm volatile("mbarrier.arrive.release.cta.shared::cta.b64 _, [%0];"
                 :: "r"(mbar) : "memory");
}

__device__ __forceinline__ float sigf(float v) { return 1.f / (1.f + __expf(-v)); }

__device__ __forceinline__ void sts_cvt16(uint32_t dst, float4 v0, float4 v1) {
    __half2 h[4];
    h[0] = __floats2half2_rn(v0.x, v0.y);
    h[1] = __floats2half2_rn(v0.z, v0.w);
    h[2] = __floats2half2_rn(v1.x, v1.y);
    h[3] = __floats2half2_rn(v1.z, v1.w);
    uint4 u = *(uint4*)h;
    asm volatile("st.shared.v4.b32 [%0], {%1,%2,%3,%4};"
                 :: "r"(dst), "r"(u.x), "r"(u.y), "r"(u.z), "r"(u.w));
}

// ---------------- fp16 GEMM + bias + sigmoid; decoupled full/empty mbarriers ----------------
// grid = (2, 128, 16); dead tiles exit immediately.
__global__ __launch_bounds__(THREADS, 2)
void gemm_kernel(const float* __restrict__ x,
                 const float* __restrict__ bias, float* __restrict__ out) {
    const int e = blockIdx.z;
    const int rows = g_counts[e];
    const int m_start = blockIdx.y * BM;
    if (m_start >= rows) return;
    const int n_start = blockIdx.x * BN;
    const int base = g_off[e];

    extern __shared__ char smem[];
    const uint32_t sb = smem_u32(smem);
    float* bsm = (float*)(smem + BIAS_OFF);
    int*   prm = (int*)(smem + PRM_OFF);

    const int t    = threadIdx.x;
    const int lane = t & 31;
    const int wid  = t >> 5;
    const int g    = lane >> 2;
    const int tig  = lane & 3;
    const int g2   = lane >> 3;
    const int lr   = lane & 7;
    const int warp_m = (wid & 1) * 32;
    const int warp_n = (wid >> 1) * 32;

    #define FULLB(s)  (sb + MBAR_OFF + (s) * 8)
    #define EMPTYB(s) (sb + MBAR_OFF + 32 + (s) * 8)

    if (t < BN) bsm[t] = bias[e * NO + n_start + t];
    if (t < BM) {
        int m = m_start + t;
        prm[t] = (m < rows) ? g_perm[base + m] : g_perm[base + m_start];
    }
    if (t == 0) {
        #pragma unroll
        for (int s = 0; s < STAGES; s++) {
            asm volatile("mbarrier.init.shared.b64 [%0], %1;"
                         :: "r"(FULLB(s)), "r"((uint32_t)THREADS) : "memory");
            asm volatile("mbarrier.init.shared.b64 [%0], %1;"
                         :: "r"(EMPTYB(s)), "r"((uint32_t)THREADS) : "memory");
        }
    }
    __syncthreads();

    // A staging: thread t -> row t>>2, chunk t&3 (8 fp32 -> 8 fp16 = 16B), swizzled dst
    const int arow = t >> 2;
    const float* agp = x + (size_t)prm[arow] * NH + (t & 3) * 8;
    const uint32_t adst = (uint32_t)(arow * 64 + SWZ(arow, t & 3) * 16);
    // B bulk source: contiguous, pre-swizzled 8KB per slab
    const __half* bsrc = W16t + ((size_t)(e * 2 + blockIdx.x) * NSLAB) * (128 * 32);

    // ldmatrix row bases + swizzle keys
    uint32_t arb[2], asw[2], brb[2], bsw[2];
    const uint32_t cba = g2 >> 1;
    const uint32_t cbb = g2 & 1;
    #pragma unroll
    for (int mf = 0; mf < 2; mf++) {
        const int r = warp_m + mf * 16 + (g2 & 1) * 8 + lr;
        arb[mf] = (uint32_t)(r * 64);
        asw[mf] = (uint32_t)((r >> 1) & 3);
    }
    #pragma unroll
    for (int p = 0; p < 2; p++) {
        const int r = warp_n + p * 16 + (g2 >> 1) * 8 + lr;
        brb[p] = (uint32_t)(r * 64);
        bsw[p] = (uint32_t)((r >> 1) & 3);
    }

    float acc[2][4][4];
    #pragma unroll
    for (int i = 0; i < 2; i++)
        #pragma unroll
        for (int j = 0; j < 4; j++)
            #pragma unroll
            for (int q = 0; q < 4; q++) acc[i][j][q] = 0.f;

    // fill stage s with slab ks: STS(A) then arrive full (t0: arrive.expect_tx + B bulk)
    auto fill = [&](int ks, int s, float4 v0, float4 v1) {
        sts_cvt16(sb + A_OFF + s * A_STAGE_B + adst, v0, v1);
        if (t == 0) {
            asm volatile("mbarrier.arrive.expect_tx.release.cta.shared::cta.b64 _, [%0], %1;"
                         :: "r"(FULLB(s)), "r"((uint32_t)B_STAGE_B) : "memory");
            asm volatile(
                "cp.async.bulk.shared::cluster.global.mbarrier::complete_tx::bytes "
                "[%0], [%1], %2, [%3];"
                :: "r"(sb + B_OFF + s * B_STAGE_B), "l"(bsrc + (size_t)ks * (128 * 32)),
                   "r"((uint32_t)B_STAGE_B), "r"(FULLB(s)) : "memory");
        } else {
            mbar_arrive(FULLB(s));
        }
    };

    // prologue: fill stages 0..2 (slabs 0..2); no empty waits (first use)
    #pragma unroll
    for (int s = 0; s < STAGES - 1; s++) {
        float4 v0 = ((const float4*)(agp + s * BKS))[0];
        float4 v1 = ((const float4*)(agp + s * BKS))[1];
        fill(s, s, v0, v1);
    }
    // preload regs for slab 3 (staged at bottom of iteration 0)
    float4 p0 = ((const float4*)(agp + (STAGES - 1) * BKS))[0];
    float4 p1 = ((const float4*)(agp + (STAGES - 1) * BKS))[1];

    for (int ks = 0; ks < NSLAB; ks++) {
        const int s = ks & (STAGES - 1);
        mbar_wait(FULLB(s), (ks >> 2) & 1);

        // prefetch A LDG for slab ks+4 (consumed at bottom of NEXT iteration)
        float4 n0, n1;
        if (ks + STAGES < NSLAB) {
            n0 = ((const float4*)(agp + (ks + STAGES) * BKS))[0];
            n1 = ((const float4*)(agp + (ks + STAGES) * BKS))[1];
        }

        const uint32_t ab = sb + A_OFF + s * A_STAGE_B;
        const uint32_t bb = sb + B_OFF + s * B_STAGE_B;
        #pragma unroll
        for (int kk = 0; kk < 2; kk++) {
            uint32_t a[2][4], b[2][4];
            #pragma unroll
            for (int mf = 0; mf < 2; mf++)
                ldsm_x4(a[mf], ab + arb[mf] + (((cba | (kk << 1)) ^ asw[mf]) << 4));
            #pragma unroll
            for (int p = 0; p < 2; p++)
                ldsm_x4(b[p], bb + brb[p] + (((cbb | (kk << 1)) ^ bsw[p]) << 4));
            #pragma unroll
            for (int mf = 0; mf < 2; mf++)
                #pragma unroll
                for (int nf = 0; nf < 4; nf++)
                    mma_f16(acc[mf][nf], a[mf], b[nf >> 1][(nf & 1) * 2],
                            b[nf >> 1][(nf & 1) * 2 + 1]);
        }
        mbar_arrive(EMPTYB(s));   // LDSM results are in registers; stage s consumable

        // fill stage for slab ks+3 from regs loaded one full iteration ago
        const int ksn = ks + STAGES - 1;
        if (ksn < NSLAB) {
            const int sn = ksn & (STAGES - 1);
            if (ksn >= STAGES)   // stage previously used by slab ksn-4: wait all consumed
                mbar_wait(EMPTYB(sn), ((ksn - STAGES) >> 2) & 1);
            fill(ksn, sn, p0, p1);
        }
        p0 = n0;
        p1 = n1;
    }

    // epilogue: bias + sigmoid, scatter rows through prm
    #pragma unroll
    for (int mf = 0; mf < 2; mf++) {
        #pragma unroll
        for (int h = 0; h < 2; h++) {
            const int rl = warp_m + mf * 16 + g + h * 8;
            if (m_start + rl < rows) {
                const int orow = prm[rl];
                #pragma unroll
                for (int nf = 0; nf < 4; nf++) {
                    const int col = warp_n + nf * 8 + 2 * tig;
                    float v0 = acc[mf][nf][h * 2 + 0] + bsm[col];
                    float v1 = acc[mf][nf][h * 2 + 1] + bsm[col + 1];
                    float2 o;
                    o.x = sigf(v0);
                    o.y = sigf(v1);
                    *(float2*)&out[(size_t)orow * NO + n_start + col] = o;
                }
            }
        }
    }
}

extern "C" void kernel_launch(void* const* d_in, const int* in_sizes, int n_in,
                              void* d_out, int out_size) {
    const float* x    = (const float*)d_in[0];   // [B, H]
    const float* W    = (const float*)d_in[1];   // [E, O, H]
    const float* bias = (const float*)d_in[2];   // [E, O]
    const int*   num  = (const int*)d_in[3];     // [B]    int32
    const int*   c    = (const int*)d_in[4];     // [CMAP] int32
    float* out = (float*)d_out;                  // [B, O]

    const int cmap_n = in_sizes[4];

    cudaFuncSetAttribute(gemm_kernel, cudaFuncAttributeMaxDynamicSharedMemorySize,
                         SMEM_TOTAL);

    prep_kernel<<<2049, 256>>>(W, num, c, cmap_n);

    dim3 grid(NO / BN, NB / BM, NE);   // (2, 128, 16)
    gemm_kernel<<<grid, THREADS, SMEM_TOTAL>>>(x, bias, out);
}